// round 6
// baseline (speedup 1.0000x reference)
#include <cuda_runtime.h>
#include <cuda_fp16.h>
#include <cstdint>

// ChunkStickyRouter on GB300 (sm_103a) — mma.sync fp16 3-product split,
// lo-products accumulated in f16 (probe legacy HMMA f16-acc rate)
// B=8, S=4096, D=2048, H=1024, E=8, CHUNK=128, TAU=0.7

#define B_  8
#define S_  4096
#define D_  2048
#define H_  1024
#define E_  8
#define CHUNK_ 128
#define NCHUNK_ 256
#define TAU_ 0.7f

// GEMM1 tiling
#define BM_ 128
#define BN_ 128
#define BK_ 32
#define NKC_ (D_ / BK_)        // 64
#define NTHR_ 512
#define ROWB_ 80
#define SPLIT_SZ_ (128 * ROWB_)          // 10240 B
#define AREG_   (2 * SPLIT_SZ_)          // 20480 (A hi+lo)
#define STAGE_SZ_ (4 * SPLIT_SZ_)        // 40960 (A hi/lo + B hi/lo)
#define SM_B1_   (3 * STAGE_SZ_)         // 122880
#define SM_PART_ (SM_B1_ + 512)
#define SMEM_TOTAL_ (SM_PART_ + 1024)    // 124416

__device__ __half g_x_hi[(size_t)B_ * S_ * D_];
__device__ __half g_x_lo[(size_t)B_ * S_ * D_];
__device__ __half g_w1t_hi[(size_t)H_ * D_];      // [n][k]
__device__ __half g_w1t_lo[(size_t)H_ * D_];
__device__ float  g_hsum[NCHUNK_ * H_];
__device__ float  g_clogits[NCHUNK_ * E_];
__device__ int    g_eidx[NCHUNK_];

// ---------------- PTX helpers ----------------
__device__ __forceinline__ uint32_t smem_to_u32(const void* p) {
    uint32_t a;
    asm("{ .reg .u64 t; cvta.to.shared.u64 t, %1; cvt.u32.u64 %0, t; }" : "=r"(a) : "l"(p));
    return a;
}
#define CP_ASYNC16(dst, src) \
    asm volatile("cp.async.cg.shared.global [%0], [%1], 16;" :: "r"(dst), "l"(src))
#define CP_COMMIT() asm volatile("cp.async.commit_group;" ::: "memory")
#define CP_WAIT1()  asm volatile("cp.async.wait_group 1;" ::: "memory")

#define LDSM4(r, a) \
    asm volatile("ldmatrix.sync.aligned.m8n8.x4.shared.b16 {%0,%1,%2,%3}, [%4];" \
        : "=r"((r)[0]), "=r"((r)[1]), "=r"((r)[2]), "=r"((r)[3]) : "r"(a))
#define LDSM2(r, a) \
    asm volatile("ldmatrix.sync.aligned.m8n8.x2.shared.b16 {%0,%1}, [%2];" \
        : "=r"((r)[0]), "=r"((r)[1]) : "r"(a))

// fp32-accumulate HMMA
#define MMA_F32(d, a, b) \
    asm volatile("mma.sync.aligned.m16n8k16.row.col.f32.f16.f16.f32 " \
        "{%0,%1,%2,%3}, {%4,%5,%6,%7}, {%8,%9}, {%0,%1,%2,%3};" \
        : "+f"((d)[0]), "+f"((d)[1]), "+f"((d)[2]), "+f"((d)[3]) \
        : "r"((a)[0]), "r"((a)[1]), "r"((a)[2]), "r"((a)[3]), "r"((b)[0]), "r"((b)[1]))

// fp16-accumulate HMMA (for the small correction products)
#define MMA_F16(d, a, b) \
    asm volatile("mma.sync.aligned.m16n8k16.row.col.f16.f16.f16.f16 " \
        "{%0,%1}, {%2,%3,%4,%5}, {%6,%7}, {%0,%1};" \
        : "+r"((d)[0]), "+r"((d)[1]) \
        : "r"((a)[0]), "r"((a)[1]), "r"((a)[2]), "r"((a)[3]), "r"((b)[0]), "r"((b)[1]))

// ---------------- prepass: split fp32 -> fp16 hi/lo ----------------
__global__ void split_x(const float4* __restrict__ x4) {
    size_t i = (size_t)blockIdx.x * blockDim.x + threadIdx.x;
    float4 v = x4[i];
    __half hx = __float2half_rn(v.x), hy = __float2half_rn(v.y);
    __half hz = __float2half_rn(v.z), hw = __float2half_rn(v.w);
    __half lx = __float2half_rn(v.x - __half2float(hx));
    __half ly = __float2half_rn(v.y - __half2float(hy));
    __half lz = __float2half_rn(v.z - __half2float(hz));
    __half lw = __float2half_rn(v.w - __half2float(hw));
    ((__half2*)g_x_hi)[i * 2 + 0] = __halves2half2(hx, hy);
    ((__half2*)g_x_hi)[i * 2 + 1] = __halves2half2(hz, hw);
    ((__half2*)g_x_lo)[i * 2 + 0] = __halves2half2(lx, ly);
    ((__half2*)g_x_lo)[i * 2 + 1] = __halves2half2(lz, lw);
}

__global__ void split_w1(const float* __restrict__ W1) {
    __shared__ float t[32][33];
    int n0 = blockIdx.x * 32, k0 = blockIdx.y * 32;
    int tx = threadIdx.x, ty = threadIdx.y;
    #pragma unroll
    for (int i = 0; i < 4; i++)
        t[ty + i * 8][tx] = W1[(size_t)(k0 + ty + i * 8) * H_ + n0 + tx];
    __syncthreads();
    #pragma unroll
    for (int i = 0; i < 4; i++) {
        int n = ty + i * 8, k = tx;
        float v = t[k][n];
        __half hi = __float2half_rn(v);
        __half lo = __float2half_rn(v - __half2float(hi));
        g_w1t_hi[(size_t)(n0 + n) * D_ + k0 + k] = hi;
        g_w1t_lo[(size_t)(n0 + n) * D_ + k0 + k] = lo;
    }
}

// ---------------- GEMM1 ----------------
__global__ __launch_bounds__(NTHR_, 1)
void gemm1_mma(const float* __restrict__ b1) {
    extern __shared__ __align__(1024) char smem[];
    const uint32_t sb = smem_to_u32(smem);
    const int tid = threadIdx.x;
    const int lane = tid & 31, wid = tid >> 5;      // 16 warps
    const int wm = wid & 1, wn = wid >> 1;          // 2(m) x 8(n), warp tile 64x16
    const int n0 = blockIdx.x * BN_;
    const int chunk = blockIdx.y;
    const int m0 = chunk * BM_;

    if (tid < BN_) ((float*)(smem + SM_B1_))[tid] = b1[n0 + tid];

    // cp.async: 2 A-chunks + 2 B-chunks of 16B per thread
    const char* srcA[2]; uint32_t dstA[2];
    const char* srcB[2]; uint32_t dstB[2];
    #pragma unroll
    for (int j = 0; j < 2; j++) {
        int q = tid + j * NTHR_;               // 0..1023
        int split = q >> 9, row = (q >> 2) & 127, k16 = q & 3;
        const __half* ba = split ? g_x_lo : g_x_hi;
        srcA[j] = (const char*)(ba + (size_t)(m0 + row) * D_ + k16 * 8);
        dstA[j] = sb + split * SPLIT_SZ_ + row * ROWB_ + k16 * 16;
        const __half* bw = split ? g_w1t_lo : g_w1t_hi;
        srcB[j] = (const char*)(bw + (size_t)(n0 + row) * D_ + k16 * 8);
        dstB[j] = sb + AREG_ + split * SPLIT_SZ_ + row * ROWB_ + k16 * 16;
    }

    const uint32_t a_off = (uint32_t)((wm * 64 + (lane & 15)) * ROWB_ + (lane >> 4) * 16);
    const uint32_t b_off = (uint32_t)(AREG_ + (wn * 16 + (lane & 7)) * ROWB_ + ((lane >> 3) & 1) * 16);

    float    accH[4][2][4];   // hi product, fp32
    uint32_t accL[4][2][2];   // lo products, f16x2
    #pragma unroll
    for (int a = 0; a < 4; a++)
        #pragma unroll
        for (int b = 0; b < 2; b++) {
            #pragma unroll
            for (int c = 0; c < 4; c++) accH[a][b][c] = 0.f;
            accL[a][b][0] = 0u; accL[a][b][1] = 0u;
        }

    #pragma unroll
    for (int s = 0; s < 2; s++) {
        uint32_t sbase = s * STAGE_SZ_;
        #pragma unroll
        for (int j = 0; j < 2; j++) {
            CP_ASYNC16(dstA[j] + sbase, srcA[j] + s * 64);
            CP_ASYNC16(dstB[j] + sbase, srcB[j] + s * 64);
        }
        CP_COMMIT();
    }

    int buf = 0;
    for (int ck = 0; ck < NKC_; ck++) {
        CP_WAIT1();
        __syncthreads();

        if (ck + 2 < NKC_) {
            int nb = buf + 2; if (nb >= 3) nb -= 3;
            uint32_t sbase = nb * STAGE_SZ_;
            #pragma unroll
            for (int j = 0; j < 2; j++) {
                CP_ASYNC16(dstA[j] + sbase, srcA[j] + (size_t)(ck + 2) * 64);
                CP_ASYNC16(dstB[j] + sbase, srcB[j] + (size_t)(ck + 2) * 64);
            }
        }
        CP_COMMIT();

        const uint32_t bufbase = sb + buf * STAGE_SZ_;
        #pragma unroll
        for (int kk = 0; kk < 2; kk++) {
            uint32_t ah[4][4], al[4][4], bh[2][2], bl[2][2];
            uint32_t ab = bufbase + a_off + kk * 32;
            uint32_t bb = bufbase + b_off + kk * 32;
            #pragma unroll
            for (int mt = 0; mt < 4; mt++) LDSM4(ah[mt], ab + mt * (16 * ROWB_));
            #pragma unroll
            for (int mt = 0; mt < 4; mt++) LDSM4(al[mt], ab + SPLIT_SZ_ + mt * (16 * ROWB_));
            #pragma unroll
            for (int nt = 0; nt < 2; nt++) {
                LDSM2(bh[nt], bb + nt * (8 * ROWB_));
                LDSM2(bl[nt], bb + SPLIT_SZ_ + nt * (8 * ROWB_));
            }
            #pragma unroll
            for (int mt = 0; mt < 4; mt++)
                #pragma unroll
                for (int nt = 0; nt < 2; nt++) {
                    MMA_F32(accH[mt][nt], ah[mt], bh[nt]);
                    MMA_F16(accL[mt][nt], ah[mt], bl[nt]);
                    MMA_F16(accL[mt][nt], al[mt], bh[nt]);
                }
        }
        buf++; if (buf >= 3) buf = 0;
    }

    // ---- epilogue: merge lo, +bias, relu, chunk column-sum ----
    const float* sb1f = (const float*)(smem + SM_B1_);
    float csum[2][2];
    csum[0][0] = csum[0][1] = csum[1][0] = csum[1][1] = 0.f;
    #pragma unroll
    for (int nt = 0; nt < 2; nt++) {
        int col = wn * 16 + nt * 8 + (lane & 3) * 2;
        float bv0 = sb1f[col], bv1 = sb1f[col + 1];
        #pragma unroll
        for (int mt = 0; mt < 4; mt++) {
            __half2 l0 = *(__half2*)&accL[mt][nt][0];
            __half2 l1 = *(__half2*)&accL[mt][nt][1];
            float v0 = accH[mt][nt][0] + __low2float(l0)  + bv0;
            float v1 = accH[mt][nt][1] + __high2float(l0) + bv1;
            float v2 = accH[mt][nt][2] + __low2float(l1)  + bv0;
            float v3 = accH[mt][nt][3] + __high2float(l1) + bv1;
            csum[nt][0] += fmaxf(v0, 0.f) + fmaxf(v2, 0.f);
            csum[nt][1] += fmaxf(v1, 0.f) + fmaxf(v3, 0.f);
        }
    }
    #pragma unroll
    for (int nt = 0; nt < 2; nt++)
        #pragma unroll
        for (int r = 0; r < 2; r++) {
            csum[nt][r] += __shfl_xor_sync(0xffffffffu, csum[nt][r], 4);
            csum[nt][r] += __shfl_xor_sync(0xffffffffu, csum[nt][r], 8);
            csum[nt][r] += __shfl_xor_sync(0xffffffffu, csum[nt][r], 16);
        }
    float* part = (float*)(smem + SM_PART_);    // [2][128]
    __syncthreads();
    if (lane < 4) {
        #pragma unroll
        for (int nt = 0; nt < 2; nt++) {
            int col = wn * 16 + nt * 8 + lane * 2;
            part[wm * BN_ + col] = csum[nt][0];
            part[wm * BN_ + col + 1] = csum[nt][1];
        }
    }
    __syncthreads();
    if (tid < BN_)
        g_hsum[(size_t)chunk * H_ + n0 + tid] = part[tid] + part[BN_ + tid];
}

// ---------------- GEMM2 ----------------
__global__ void gemm2_logits(const float* __restrict__ W2,
                             const float* __restrict__ b2) {
    const int bc = blockIdx.x;
    const int tid = threadIdx.x;
    const float* hs = g_hsum + (size_t)bc * H_;

    float acc[E_];
    #pragma unroll
    for (int e = 0; e < E_; e++) acc[e] = 0.f;

    for (int j = tid; j < H_; j += 128) {
        float h = hs[j];
        float4 w0 = *(const float4*)(W2 + (size_t)j * E_);
        float4 w1 = *(const float4*)(W2 + (size_t)j * E_ + 4);
        acc[0] += h * w0.x; acc[1] += h * w0.y; acc[2] += h * w0.z; acc[3] += h * w0.w;
        acc[4] += h * w1.x; acc[5] += h * w1.y; acc[6] += h * w1.z; acc[7] += h * w1.w;
    }
    #pragma unroll
    for (int off = 16; off; off >>= 1)
        #pragma unroll
        for (int e = 0; e < E_; e++)
            acc[e] += __shfl_down_sync(0xffffffffu, acc[e], off);

    __shared__ float sred[4][E_];
    if ((tid & 31) == 0) {
        #pragma unroll
        for (int e = 0; e < E_; e++) sred[tid >> 5][e] = acc[e];
    }
    __syncthreads();
    if (tid < E_) {
        float s = sred[0][tid] + sred[1][tid] + sred[2][tid] + sred[3][tid];
        g_clogits[bc * E_ + tid] = s * (1.0f / (float)CHUNK_) + b2[tid];
    }
}

__global__ void hysteresis_scan(float* __restrict__ out, int out_size) {
    int b = threadIdx.x;
    if (b >= B_) return;
    const float* cl = g_clogits + b * 32 * E_;

    int prev = 0;
    {
        float best = cl[0];
        #pragma unroll
        for (int e = 1; e < E_; e++)
            if (cl[e] > best) { best = cl[e]; prev = e; }
    }
    g_eidx[b * 32] = prev;

    for (int c = 1; c < 32; c++) {
        const float* l = cl + c * E_;
        int ce = 0; float best = l[0];
        #pragma unroll
        for (int e = 1; e < E_; e++)
            if (l[e] > best) { best = l[e]; ce = e; }
        if (l[ce] - l[prev] > TAU_) prev = ce;
        g_eidx[b * 32 + c] = prev;
    }
    if (out_size >= B_ * S_ * E_ + NCHUNK_) {
        for (int c = 0; c < 32; c++)
            out[B_ * S_ * E_ + b * 32 + c] = (float)g_eidx[b * 32 + c];
    }
}

__global__ void fill_routing(float* __restrict__ out) {
    int q = blockIdx.x * blockDim.x + threadIdx.x;
    int token = q >> 1;
    int e0 = (q & 1) * 4;
    int idx = g_eidx[token >> 7];
    float4 v;
    v.x = (e0 + 0 == idx) ? 1.0f : 0.0f;
    v.y = (e0 + 1 == idx) ? 1.0f : 0.0f;
    v.z = (e0 + 2 == idx) ? 1.0f : 0.0f;
    v.w = (e0 + 3 == idx) ? 1.0f : 0.0f;
    ((float4*)out)[q] = v;
}

extern "C" void kernel_launch(void* const* d_in, const int* in_sizes, int n_in,
                              void* d_out, int out_size) {
    const float* x  = (const float*)d_in[0];
    const float* W1 = (const float*)d_in[1];
    const float* b1 = (const float*)d_in[2];
    const float* W2 = (const float*)d_in[3];
    const float* b2 = (const float*)d_in[4];
    float* out = (float*)d_out;

    cudaFuncSetAttribute(gemm1_mma, cudaFuncAttributeMaxDynamicSharedMemorySize, SMEM_TOTAL_);

    split_x<<<(B_ * S_ * D_ / 4) / 256, 256>>>((const float4*)x);
    split_w1<<<dim3(H_ / 32, D_ / 32), dim3(32, 8)>>>(W1);
    gemm1_mma<<<dim3(H_ / BN_, NCHUNK_), NTHR_, SMEM_TOTAL_>>>(b1);
    gemm2_logits<<<NCHUNK_, 128>>>(W2, b2);
    hysteresis_scan<<<1, 32>>>(out, out_size);
    fill_routing<<<(B_ * S_ * E_ / 4) / 256, 256>>>(out);
}

// round 7
// speedup vs baseline: 2.8251x; 2.8251x over previous
#include <cuda_runtime.h>
#include <cuda_fp16.h>
#include <cstdint>

// ChunkStickyRouter on GB300 (sm_103a) — plain fp16 mma.sync GEMM1 (1 product),
// fp32 accumulate; chunk-mean averaging keeps logit error ~1e-5.
// B=8, S=4096, D=2048, H=1024, E=8, CHUNK=128, TAU=0.7

#define B_  8
#define S_  4096
#define D_  2048
#define H_  1024
#define E_  8
#define CHUNK_ 128
#define NCHUNK_ 256
#define TAU_ 0.7f

// GEMM1 tiling
#define BM_ 128
#define BN_ 128
#define BK_ 32
#define NKC_ (D_ / BK_)        // 64
#define NTHR_ 256
#define ROWB_ 80               // smem row stride (bytes): conflict-free LDSM
#define ATILE_ (128 * ROWB_)           // 10240 B
#define BTILE_ (128 * ROWB_)           // 10240 B
#define STAGE_SZ_ (ATILE_ + BTILE_)    // 20480
#define SM_B1_   (3 * STAGE_SZ_)       // 61440
#define SM_PART_ (SM_B1_ + 512)
#define SMEM_TOTAL_ (SM_PART_ + 1024)  // 62976  -> 2 CTAs/SM

__device__ __half g_xh[(size_t)B_ * S_ * D_];     // x as fp16
__device__ __half g_w1t[(size_t)H_ * D_];         // W1^T as fp16, [n][k]
__device__ float  g_hsum[NCHUNK_ * H_];
__device__ float  g_clogits[NCHUNK_ * E_];
__device__ int    g_eidx[NCHUNK_];

// ---------------- PTX helpers ----------------
__device__ __forceinline__ uint32_t smem_to_u32(const void* p) {
    uint32_t a;
    asm("{ .reg .u64 t; cvta.to.shared.u64 t, %1; cvt.u32.u64 %0, t; }" : "=r"(a) : "l"(p));
    return a;
}
#define CP_ASYNC16(dst, src) \
    asm volatile("cp.async.cg.shared.global [%0], [%1], 16;" :: "r"(dst), "l"(src))
#define CP_COMMIT() asm volatile("cp.async.commit_group;" ::: "memory")
#define CP_WAIT1()  asm volatile("cp.async.wait_group 1;" ::: "memory")

#define LDSM4(r, a) \
    asm volatile("ldmatrix.sync.aligned.m8n8.x4.shared.b16 {%0,%1,%2,%3}, [%4];" \
        : "=r"((r)[0]), "=r"((r)[1]), "=r"((r)[2]), "=r"((r)[3]) : "r"(a))
#define LDSM2(r, a) \
    asm volatile("ldmatrix.sync.aligned.m8n8.x2.shared.b16 {%0,%1}, [%2];" \
        : "=r"((r)[0]), "=r"((r)[1]) : "r"(a))

#define MMA_F32(d, a, b) \
    asm volatile("mma.sync.aligned.m16n8k16.row.col.f32.f16.f16.f32 " \
        "{%0,%1,%2,%3}, {%4,%5,%6,%7}, {%8,%9}, {%0,%1,%2,%3};" \
        : "+f"((d)[0]), "+f"((d)[1]), "+f"((d)[2]), "+f"((d)[3]) \
        : "r"((a)[0]), "r"((a)[1]), "r"((a)[2]), "r"((a)[3]), "r"((b)[0]), "r"((b)[1]))

// ---------------- prepass: fp32 -> fp16 ----------------
__global__ void cvt_x(const float4* __restrict__ x4) {
    size_t i = (size_t)blockIdx.x * blockDim.x + threadIdx.x;   // 16M float4
    float4 v = x4[i];
    __half2 h0 = __floats2half2_rn(v.x, v.y);
    __half2 h1 = __floats2half2_rn(v.z, v.w);
    ((__half2*)g_xh)[i * 2 + 0] = h0;
    ((__half2*)g_xh)[i * 2 + 1] = h1;
}

// W1 [k=2048][n=1024] fp32 -> W1^T [n][k] fp16
__global__ void cvt_w1(const float* __restrict__ W1) {
    __shared__ float t[32][33];
    int n0 = blockIdx.x * 32, k0 = blockIdx.y * 32;
    int tx = threadIdx.x, ty = threadIdx.y;
    #pragma unroll
    for (int i = 0; i < 4; i++)
        t[ty + i * 8][tx] = W1[(size_t)(k0 + ty + i * 8) * H_ + n0 + tx];
    __syncthreads();
    #pragma unroll
    for (int i = 0; i < 4; i++) {
        int n = ty + i * 8, k = tx;
        g_w1t[(size_t)(n0 + n) * D_ + k0 + k] = __float2half_rn(t[k][n]);
    }
}

// ---------------- GEMM1: relu(x@W1+b1) with fused chunk column-sum ----------------
__global__ __launch_bounds__(NTHR_, 2)
void gemm1_mma(const float* __restrict__ b1) {
    extern __shared__ __align__(1024) char smem[];
    const uint32_t sb = smem_to_u32(smem);
    const int tid = threadIdx.x;
    const int lane = tid & 31, wid = tid >> 5;      // 8 warps
    const int wm = wid & 1, wn = wid >> 1;          // 2(m) x 4(n), warp tile 64x32
    const int n0 = blockIdx.x * BN_;
    const int chunk = blockIdx.y;
    const int m0 = chunk * BM_;

    if (tid < BN_) ((float*)(smem + SM_B1_))[tid] = b1[n0 + tid];

    // cp.async: 2 A-chunks + 2 B-chunks of 16B per thread (tile = 512 chunks each)
    const char* srcA[2]; uint32_t dstA[2];
    const char* srcB[2]; uint32_t dstB[2];
    #pragma unroll
    for (int j = 0; j < 2; j++) {
        int q = tid + j * NTHR_;               // 0..511
        int row = q >> 2, k16 = q & 3;
        srcA[j] = (const char*)(g_xh + (size_t)(m0 + row) * D_ + k16 * 8);
        dstA[j] = sb + row * ROWB_ + k16 * 16;
        srcB[j] = (const char*)(g_w1t + (size_t)(n0 + row) * D_ + k16 * 8);
        dstB[j] = sb + ATILE_ + row * ROWB_ + k16 * 16;
    }

    const uint32_t a_off = (uint32_t)((wm * 64 + (lane & 15)) * ROWB_ + (lane >> 4) * 16);
    const uint32_t b_off = (uint32_t)(ATILE_ + (wn * 32 + (lane & 7)) * ROWB_ + ((lane >> 3) & 1) * 16);

    float acc[4][4][4];
    #pragma unroll
    for (int a = 0; a < 4; a++)
        #pragma unroll
        for (int b = 0; b < 4; b++)
            #pragma unroll
            for (int c = 0; c < 4; c++) acc[a][b][c] = 0.f;

    #pragma unroll
    for (int s = 0; s < 2; s++) {
        uint32_t sbase = s * STAGE_SZ_;
        #pragma unroll
        for (int j = 0; j < 2; j++) {
            CP_ASYNC16(dstA[j] + sbase, srcA[j] + s * 64);
            CP_ASYNC16(dstB[j] + sbase, srcB[j] + s * 64);
        }
        CP_COMMIT();
    }

    int buf = 0;
    for (int ck = 0; ck < NKC_; ck++) {
        CP_WAIT1();
        __syncthreads();

        if (ck + 2 < NKC_) {
            int nb = buf + 2; if (nb >= 3) nb -= 3;
            uint32_t sbase = nb * STAGE_SZ_;
            #pragma unroll
            for (int j = 0; j < 2; j++) {
                CP_ASYNC16(dstA[j] + sbase, srcA[j] + (size_t)(ck + 2) * 64);
                CP_ASYNC16(dstB[j] + sbase, srcB[j] + (size_t)(ck + 2) * 64);
            }
        }
        CP_COMMIT();

        const uint32_t bufbase = sb + buf * STAGE_SZ_;
        #pragma unroll
        for (int kk = 0; kk < 2; kk++) {
            uint32_t ah[4][4], bh[4][2];
            uint32_t ab = bufbase + a_off + kk * 32;
            uint32_t bb = bufbase + b_off + kk * 32;
            #pragma unroll
            for (int mt = 0; mt < 4; mt++) LDSM4(ah[mt], ab + mt * (16 * ROWB_));
            #pragma unroll
            for (int nt = 0; nt < 4; nt++) LDSM2(bh[nt], bb + nt * (8 * ROWB_));
            #pragma unroll
            for (int mt = 0; mt < 4; mt++)
                #pragma unroll
                for (int nt = 0; nt < 4; nt++)
                    MMA_F32(acc[mt][nt], ah[mt], bh[nt]);
        }
        buf++; if (buf >= 3) buf = 0;
    }

    // ---- epilogue: relu(acc + b1), chunk column-sums ----
    const float* sb1f = (const float*)(smem + SM_B1_);
    float csum[4][2];
    #pragma unroll
    for (int nt = 0; nt < 4; nt++) { csum[nt][0] = 0.f; csum[nt][1] = 0.f; }
    #pragma unroll
    for (int nt = 0; nt < 4; nt++) {
        int col = wn * 32 + nt * 8 + (lane & 3) * 2;
        float bv0 = sb1f[col], bv1 = sb1f[col + 1];
        #pragma unroll
        for (int mt = 0; mt < 4; mt++) {
            csum[nt][0] += fmaxf(acc[mt][nt][0] + bv0, 0.f) + fmaxf(acc[mt][nt][2] + bv0, 0.f);
            csum[nt][1] += fmaxf(acc[mt][nt][1] + bv1, 0.f) + fmaxf(acc[mt][nt][3] + bv1, 0.f);
        }
    }
    #pragma unroll
    for (int nt = 0; nt < 4; nt++)
        #pragma unroll
        for (int r = 0; r < 2; r++) {
            csum[nt][r] += __shfl_xor_sync(0xffffffffu, csum[nt][r], 4);
            csum[nt][r] += __shfl_xor_sync(0xffffffffu, csum[nt][r], 8);
            csum[nt][r] += __shfl_xor_sync(0xffffffffu, csum[nt][r], 16);
        }
    float* part = (float*)(smem + SM_PART_);    // [2][128]
    __syncthreads();
    if (lane < 4) {
        #pragma unroll
        for (int nt = 0; nt < 4; nt++) {
            int col = wn * 32 + nt * 8 + lane * 2;
            part[wm * BN_ + col] = csum[nt][0];
            part[wm * BN_ + col + 1] = csum[nt][1];
        }
    }
    __syncthreads();
    if (tid < BN_)
        g_hsum[(size_t)chunk * H_ + n0 + tid] = part[tid] + part[BN_ + tid];
}

// ---------------- GEMM2 ----------------
__global__ void gemm2_logits(const float* __restrict__ W2,
                             const float* __restrict__ b2) {
    const int bc = blockIdx.x;
    const int tid = threadIdx.x;
    const float* hs = g_hsum + (size_t)bc * H_;

    float acc[E_];
    #pragma unroll
    for (int e = 0; e < E_; e++) acc[e] = 0.f;

    for (int j = tid; j < H_; j += 128) {
        float h = hs[j];
        float4 w0 = *(const float4*)(W2 + (size_t)j * E_);
        float4 w1 = *(const float4*)(W2 + (size_t)j * E_ + 4);
        acc[0] += h * w0.x; acc[1] += h * w0.y; acc[2] += h * w0.z; acc[3] += h * w0.w;
        acc[4] += h * w1.x; acc[5] += h * w1.y; acc[6] += h * w1.z; acc[7] += h * w1.w;
    }
    #pragma unroll
    for (int off = 16; off; off >>= 1)
        #pragma unroll
        for (int e = 0; e < E_; e++)
            acc[e] += __shfl_down_sync(0xffffffffu, acc[e], off);

    __shared__ float sred[4][E_];
    if ((tid & 31) == 0) {
        #pragma unroll
        for (int e = 0; e < E_; e++) sred[tid >> 5][e] = acc[e];
    }
    __syncthreads();
    if (tid < E_) {
        float s = sred[0][tid] + sred[1][tid] + sred[2][tid] + sred[3][tid];
        g_clogits[bc * E_ + tid] = s * (1.0f / (float)CHUNK_) + b2[tid];
    }
}

__global__ void hysteresis_scan(float* __restrict__ out, int out_size) {
    int b = threadIdx.x;
    if (b >= B_) return;
    const float* cl = g_clogits + b * 32 * E_;

    int prev = 0;
    {
        float best = cl[0];
        #pragma unroll
        for (int e = 1; e < E_; e++)
            if (cl[e] > best) { best = cl[e]; prev = e; }
    }
    g_eidx[b * 32] = prev;

    for (int c = 1; c < 32; c++) {
        const float* l = cl + c * E_;
        int ce = 0; float best = l[0];
        #pragma unroll
        for (int e = 1; e < E_; e++)
            if (l[e] > best) { best = l[e]; ce = e; }
        if (l[ce] - l[prev] > TAU_) prev = ce;
        g_eidx[b * 32 + c] = prev;
    }
    if (out_size >= B_ * S_ * E_ + NCHUNK_) {
        for (int c = 0; c < 32; c++)
            out[B_ * S_ * E_ + b * 32 + c] = (float)g_eidx[b * 32 + c];
    }
}

__global__ void fill_routing(float* __restrict__ out) {
    int q = blockIdx.x * blockDim.x + threadIdx.x;
    int token = q >> 1;
    int e0 = (q & 1) * 4;
    int idx = g_eidx[token >> 7];
    float4 v;
    v.x = (e0 + 0 == idx) ? 1.0f : 0.0f;
    v.y = (e0 + 1 == idx) ? 1.0f : 0.0f;
    v.z = (e0 + 2 == idx) ? 1.0f : 0.0f;
    v.w = (e0 + 3 == idx) ? 1.0f : 0.0f;
    ((float4*)out)[q] = v;
}

extern "C" void kernel_launch(void* const* d_in, const int* in_sizes, int n_in,
                              void* d_out, int out_size) {
    const float* x  = (const float*)d_in[0];
    const float* W1 = (const float*)d_in[1];
    const float* b1 = (const float*)d_in[2];
    const float* W2 = (const float*)d_in[3];
    const float* b2 = (const float*)d_in[4];
    float* out = (float*)d_out;

    cudaFuncSetAttribute(gemm1_mma, cudaFuncAttributeMaxDynamicSharedMemorySize, SMEM_TOTAL_);

    cvt_x<<<(B_ * S_ * D_ / 4) / 256, 256>>>((const float4*)x);
    cvt_w1<<<dim3(H_ / 32, D_ / 32), dim3(32, 8)>>>(W1);
    gemm1_mma<<<dim3(H_ / BN_, NCHUNK_), NTHR_, SMEM_TOTAL_>>>(b1);
    gemm2_logits<<<NCHUNK_, 128>>>(W2, b2);
    hysteresis_scan<<<1, 32>>>(out, out_size);
    fill_routing<<<(B_ * S_ * E_ / 4) / 256, 256>>>(out);
}

// round 9
// speedup vs baseline: 3.0936x; 1.0950x over previous
#include <cuda_runtime.h>
#include <cuda_fp16.h>
#include <cstdint>

// ChunkStickyRouter on GB300 (sm_103a) — fp16 mma.sync GEMM1 with in-kernel
// fp32->fp16 conversion of x (no separate cvt_x pass).
// B=8, S=4096, D=2048, H=1024, E=8, CHUNK=128, TAU=0.7

#define B_  8
#define S_  4096
#define D_  2048
#define H_  1024
#define E_  8
#define CHUNK_ 128
#define NCHUNK_ 256
#define TAU_ 0.7f

// GEMM1 tiling
#define BM_ 128
#define BN_ 128
#define BK_ 32
#define NKC_ (D_ / BK_)        // 64
#define NTHR_ 256
#define ROWB_ 80               // smem row stride (bytes): conflict-free LDSM
#define ATILE_ (128 * ROWB_)           // 10240 B (fp16)
#define BTILE_ (128 * ROWB_)           // 10240 B (fp16)
#define STAGE_SZ_ (ATILE_ + BTILE_)    // 20480
#define SM_B1_   (3 * STAGE_SZ_)       // 61440
#define SM_PART_ (SM_B1_ + 512)
#define SMEM_TOTAL_ (SM_PART_ + 1024)  // 62976  -> 2 CTAs/SM

__device__ __half g_w1t[(size_t)H_ * D_];         // W1^T as fp16, [n][k]
__device__ float  g_hsum[NCHUNK_ * H_];
__device__ float  g_clogits[NCHUNK_ * E_];
__device__ int    g_eidx[NCHUNK_];

// ---------------- PTX helpers ----------------
__device__ __forceinline__ uint32_t smem_to_u32(const void* p) {
    uint32_t a;
    asm("{ .reg .u64 t; cvta.to.shared.u64 t, %1; cvt.u32.u64 %0, t; }" : "=r"(a) : "l"(p));
    return a;
}
// pack two fp32 -> f16x2 (lo = x, hi = y), result as u32
__device__ __forceinline__ uint32_t pack_half2(float x, float y) {
    uint32_t u;
    asm("cvt.rn.f16x2.f32 %0, %1, %2;" : "=r"(u) : "f"(y), "f"(x));
    return u;
}
#define CP_ASYNC16(dst, src) \
    asm volatile("cp.async.cg.shared.global [%0], [%1], 16;" :: "r"(dst), "l"(src))
#define CP_COMMIT() asm volatile("cp.async.commit_group;" ::: "memory")
#define CP_WAIT1()  asm volatile("cp.async.wait_group 1;" ::: "memory")

#define LDSM4(r, a) \
    asm volatile("ldmatrix.sync.aligned.m8n8.x4.shared.b16 {%0,%1,%2,%3}, [%4];" \
        : "=r"((r)[0]), "=r"((r)[1]), "=r"((r)[2]), "=r"((r)[3]) : "r"(a))
#define LDSM2(r, a) \
    asm volatile("ldmatrix.sync.aligned.m8n8.x2.shared.b16 {%0,%1}, [%2];" \
        : "=r"((r)[0]), "=r"((r)[1]) : "r"(a))

#define MMA_F32(d, a, b) \
    asm volatile("mma.sync.aligned.m16n8k16.row.col.f32.f16.f16.f32 " \
        "{%0,%1,%2,%3}, {%4,%5,%6,%7}, {%8,%9}, {%0,%1,%2,%3};" \
        : "+f"((d)[0]), "+f"((d)[1]), "+f"((d)[2]), "+f"((d)[3]) \
        : "r"((a)[0]), "r"((a)[1]), "r"((a)[2]), "r"((a)[3]), "r"((b)[0]), "r"((b)[1]))

#define STS64(addr, v0, v1) \
    asm volatile("st.shared.v2.b32 [%0], {%1, %2};" :: "r"(addr), "r"(v0), "r"(v1))

// ---------------- prepass: W1 [k][n] fp32 -> W1^T [n][k] fp16 ----------------
__global__ void cvt_w1(const float* __restrict__ W1) {
    __shared__ float t[32][33];
    int n0 = blockIdx.x * 32, k0 = blockIdx.y * 32;
    int tx = threadIdx.x, ty = threadIdx.y;
    #pragma unroll
    for (int i = 0; i < 4; i++)
        t[ty + i * 8][tx] = W1[(size_t)(k0 + ty + i * 8) * H_ + n0 + tx];
    __syncthreads();
    #pragma unroll
    for (int i = 0; i < 4; i++) {
        int n = ty + i * 8, k = tx;
        g_w1t[(size_t)(n0 + n) * D_ + k0 + k] = __float2half_rn(t[k][n]);
    }
}

// ---------------- GEMM1: relu(x@W1+b1) with fused chunk column-sum ----------------
__global__ __launch_bounds__(NTHR_, 2)
void gemm1_mma(const float* __restrict__ x, const float* __restrict__ b1) {
    extern __shared__ __align__(1024) char smem[];
    const uint32_t sb = smem_to_u32(smem);
    const int tid = threadIdx.x;
    const int lane = tid & 31, wid = tid >> 5;      // 8 warps
    const int wm = wid & 1, wn = wid >> 1;          // 2(m) x 4(n), warp tile 64x32
    const int n0 = blockIdx.x * BN_;
    const int chunk = blockIdx.y;
    const int m0 = chunk * BM_;

    if (tid < BN_) ((float*)(smem + SM_B1_))[tid] = b1[n0 + tid];

    // ---- A (x fp32, LDG prefetch): thread covers 4 float4 chunks ----
    const int a_row0 = tid >> 3;            // +32*j
    const int a_k4   = tid & 7;
    const float* srcA0 = x + (size_t)(m0 + a_row0) * D_ + a_k4 * 4;
    const uint32_t dstA0 = sb + a_row0 * ROWB_ + a_k4 * 8;   // fp16: 8B per float4

    // ---- B (w1t fp16, cp.async): 2 chunks of 16B per thread ----
    const char* srcB[2]; uint32_t dstB[2];
    #pragma unroll
    for (int j = 0; j < 2; j++) {
        int q = tid + j * NTHR_;               // 0..511
        int row = q >> 2, k16 = q & 3;
        srcB[j] = (const char*)(g_w1t + (size_t)(n0 + row) * D_ + k16 * 8);
        dstB[j] = sb + ATILE_ + row * ROWB_ + k16 * 16;
    }

    const uint32_t a_off = (uint32_t)((wm * 64 + (lane & 15)) * ROWB_ + (lane >> 4) * 16);
    const uint32_t b_off = (uint32_t)(ATILE_ + (wn * 32 + (lane & 7)) * ROWB_ + ((lane >> 3) & 1) * 16);

    float acc[4][4][4];
    #pragma unroll
    for (int a = 0; a < 4; a++)
        #pragma unroll
        for (int b = 0; b < 4; b++)
            #pragma unroll
            for (int c = 0; c < 4; c++) acc[a][b][c] = 0.f;

    float4 areg[4];

    // ---- prologue ----
    #pragma unroll
    for (int j = 0; j < 4; j++)
        areg[j] = *(const float4*)(srcA0 + (size_t)(32 * j) * D_);
    #pragma unroll
    for (int j = 0; j < 4; j++) {
        uint32_t h0 = pack_half2(areg[j].x, areg[j].y);
        uint32_t h1 = pack_half2(areg[j].z, areg[j].w);
        STS64(dstA0 + j * (32 * ROWB_), h0, h1);
    }
    #pragma unroll
    for (int j = 0; j < 4; j++)
        areg[j] = *(const float4*)(srcA0 + (size_t)(32 * j) * D_ + BK_);
    #pragma unroll
    for (int s = 0; s < 2; s++) {
        uint32_t sbase = s * STAGE_SZ_;
        #pragma unroll
        for (int j = 0; j < 2; j++)
            CP_ASYNC16(dstB[j] + sbase, srcB[j] + s * 64);
        CP_COMMIT();
    }

    int buf = 0;
    for (int ck = 0; ck < NKC_; ck++) {
        CP_WAIT1();
        __syncthreads();

        // stage A(ck+1) regs -> smem buf (ck+1)%3 ; prefetch A(ck+2); B(ck+2) cp.async
        if (ck + 1 < NKC_) {
            int nb1 = buf + 1; if (nb1 >= 3) nb1 -= 3;
            uint32_t ab = dstA0 + nb1 * STAGE_SZ_;
            #pragma unroll
            for (int j = 0; j < 4; j++) {
                uint32_t h0 = pack_half2(areg[j].x, areg[j].y);
                uint32_t h1 = pack_half2(areg[j].z, areg[j].w);
                STS64(ab + j * (32 * ROWB_), h0, h1);
            }
        }
        if (ck + 2 < NKC_) {
            #pragma unroll
            for (int j = 0; j < 4; j++)
                areg[j] = *(const float4*)(srcA0 + (size_t)(32 * j) * D_ + (size_t)(ck + 2) * BK_);
            int nb2 = buf + 2; if (nb2 >= 3) nb2 -= 3;
            uint32_t sbase = nb2 * STAGE_SZ_;
            #pragma unroll
            for (int j = 0; j < 2; j++)
                CP_ASYNC16(dstB[j] + sbase, srcB[j] + (size_t)(ck + 2) * 64);
        }
        CP_COMMIT();

        const uint32_t bufbase = sb + buf * STAGE_SZ_;
        #pragma unroll
        for (int kk = 0; kk < 2; kk++) {
            uint32_t ah[4][4], bh[4][2];
            uint32_t ab = bufbase + a_off + kk * 32;
            uint32_t bb = bufbase + b_off + kk * 32;
            #pragma unroll
            for (int mt = 0; mt < 4; mt++) LDSM4(ah[mt], ab + mt * (16 * ROWB_));
            #pragma unroll
            for (int nt = 0; nt < 4; nt++) LDSM2(bh[nt], bb + nt * (8 * ROWB_));
            #pragma unroll
            for (int mt = 0; mt < 4; mt++)
                #pragma unroll
                for (int nt = 0; nt < 4; nt++)
                    MMA_F32(acc[mt][nt], ah[mt], bh[nt]);
        }
        buf++; if (buf >= 3) buf = 0;
    }

    // ---- epilogue: relu(acc + b1), chunk column-sums ----
    const float* sb1f = (const float*)(smem + SM_B1_);
    float csum[4][2];
    #pragma unroll
    for (int nt = 0; nt < 4; nt++) { csum[nt][0] = 0.f; csum[nt][1] = 0.f; }
    #pragma unroll
    for (int nt = 0; nt < 4; nt++) {
        int col = wn * 32 + nt * 8 + (lane & 3) * 2;
        float bv0 = sb1f[col], bv1 = sb1f[col + 1];
        #pragma unroll
        for (int mt = 0; mt < 4; mt++) {
            csum[nt][0] += fmaxf(acc[mt][nt][0] + bv0, 0.f) + fmaxf(acc[mt][nt][2] + bv0, 0.f);
            csum[nt][1] += fmaxf(acc[mt][nt][1] + bv1, 0.f) + fmaxf(acc[mt][nt][3] + bv1, 0.f);
        }
    }
    #pragma unroll
    for (int nt = 0; nt < 4; nt++)
        #pragma unroll
        for (int r = 0; r < 2; r++) {
            csum[nt][r] += __shfl_xor_sync(0xffffffffu, csum[nt][r], 4);
            csum[nt][r] += __shfl_xor_sync(0xffffffffu, csum[nt][r], 8);
            csum[nt][r] += __shfl_xor_sync(0xffffffffu, csum[nt][r], 16);
        }
    float* part = (float*)(smem + SM_PART_);    // [2][128]
    __syncthreads();
    if (lane < 4) {
        #pragma unroll
        for (int nt = 0; nt < 4; nt++) {
            int col = wn * 32 + nt * 8 + lane * 2;
            part[wm * BN_ + col] = csum[nt][0];
            part[wm * BN_ + col + 1] = csum[nt][1];
        }
    }
    __syncthreads();
    if (tid < BN_)
        g_hsum[(size_t)chunk * H_ + n0 + tid] = part[tid] + part[BN_ + tid];
}

// ---------------- GEMM2 ----------------
__global__ void gemm2_logits(const float* __restrict__ W2,
                             const float* __restrict__ b2) {
    const int bc = blockIdx.x;
    const int tid = threadIdx.x;
    const float* hs = g_hsum + (size_t)bc * H_;

    float acc[E_];
    #pragma unroll
    for (int e = 0; e < E_; e++) acc[e] = 0.f;

    for (int j = tid; j < H_; j += 128) {
        float h = hs[j];
        float4 w0 = *(const float4*)(W2 + (size_t)j * E_);
        float4 w1 = *(const float4*)(W2 + (size_t)j * E_ + 4);
        acc[0] += h * w0.x; acc[1] += h * w0.y; acc[2] += h * w0.z; acc[3] += h * w0.w;
        acc[4] += h * w1.x; acc[5] += h * w1.y; acc[6] += h * w1.z; acc[7] += h * w1.w;
    }
    #pragma unroll
    for (int off = 16; off; off >>= 1)
        #pragma unroll
        for (int e = 0; e < E_; e++)
            acc[e] += __shfl_down_sync(0xffffffffu, acc[e], off);

    __shared__ float sred[4][E_];
    if ((tid & 31) == 0) {
        #pragma unroll
        for (int e = 0; e < E_; e++) sred[tid >> 5][e] = acc[e];
    }
    __syncthreads();
    if (tid < E_) {
        float s = sred[0][tid] + sred[1][tid] + sred[2][tid] + sred[3][tid];
        g_clogits[bc * E_ + tid] = s * (1.0f / (float)CHUNK_) + b2[tid];
    }
}

__global__ void hysteresis_scan(float* __restrict__ out, int out_size) {
    int b = threadIdx.x;
    if (b >= B_) return;
    const float* cl = g_clogits + b * 32 * E_;

    int prev = 0;
    {
        float best = cl[0];
        #pragma unroll
        for (int e = 1; e < E_; e++)
            if (cl[e] > best) { best = cl[e]; prev = e; }
    }
    g_eidx[b * 32] = prev;

    for (int c = 1; c < 32; c++) {
        const float* l = cl + c * E_;
        int ce = 0; float best = l[0];
        #pragma unroll
        for (int e = 1; e < E_; e++)
            if (l[e] > best) { best = l[e]; ce = e; }
        if (l[ce] - l[prev] > TAU_) prev = ce;
        g_eidx[b * 32 + c] = prev;
    }
    if (out_size >= B_ * S_ * E_ + NCHUNK_) {
        for (int c = 0; c < 32; c++)
            out[B_ * S_ * E_ + b * 32 + c] = (float)g_eidx[b * 32 + c];
    }
}

__global__ void fill_routing(float* __restrict__ out) {
    int q = blockIdx.x * blockDim.x + threadIdx.x;
    int token = q >> 1;
    int e0 = (q & 1) * 4;
    int idx = g_eidx[token >> 7];
    float4 v;
    v.x = (e0 + 0 == idx) ? 1.0f : 0.0f;
    v.y = (e0 + 1 == idx) ? 1.0f : 0.0f;
    v.z = (e0 + 2 == idx) ? 1.0f : 0.0f;
    v.w = (e0 + 3 == idx) ? 1.0f : 0.0f;
    ((float4*)out)[q] = v;
}

extern "C" void kernel_launch(void* const* d_in, const int* in_sizes, int n_in,
                              void* d_out, int out_size) {
    const float* x  = (const float*)d_in[0];
    const float* W1 = (const float*)d_in[1];
    const float* b1 = (const float*)d_in[2];
    const float* W2 = (const float*)d_in[3];
    const float* b2 = (const float*)d_in[4];
    float* out = (float*)d_out;

    cudaFuncSetAttribute(gemm1_mma, cudaFuncAttributeMaxDynamicSharedMemorySize, SMEM_TOTAL_);

    cvt_w1<<<dim3(H_ / 32, D_ / 32), dim3(32, 8)>>>(W1);
    gemm1_mma<<<dim3(H_ / BN_, NCHUNK_), NTHR_, SMEM_TOTAL_>>>(x, b1);
    gemm2_logits<<<NCHUNK_, 128>>>(W2, b2);
    hysteresis_scan<<<1, 32>>>(out, out_size);
    fill_routing<<<(B_ * S_ * E_ / 4) / 256, 256>>>(out);
}